// round 4
// baseline (speedup 1.0000x reference)
#include <cuda_runtime.h>

#define HW 262144      // 512*512
#define W  512

// cos(k*pi/16)
#define C1f 0.98078528040323044913f
#define C2f 0.92387953251128675613f
#define C3f 0.83146961230254523708f
#define C4f 0.70710678118654752440f
#define C5f 0.55557023301960222474f
#define C6f 0.38268343236508977173f
#define C7f 0.19509032201612826785f

// o[u] = sum_x a[x] * cos((2x+1)u pi/16)
__device__ __forceinline__ void dct8(const float* a, float* o) {
    float s0 = a[0] + a[7], s1 = a[1] + a[6];
    float s2 = a[2] + a[5], s3 = a[3] + a[4];
    float d0 = a[0] - a[7], d1 = a[1] - a[6];
    float d2 = a[2] - a[5], d3 = a[3] - a[4];
    float f0 = s0 + s3, f1 = s1 + s2;
    float e0 = s0 - s3, e1 = s1 - s2;
    o[0] = f0 + f1;
    o[4] = (f0 - f1) * C4f;
    o[2] = fmaf(e0, C2f,  e1 * C6f);
    o[6] = fmaf(e0, C6f, -e1 * C2f);
    o[1] = fmaf(d0, C1f, fmaf(d1,  C3f, fmaf(d2,  C5f,  d3 * C7f)));
    o[3] = fmaf(d0, C3f, fmaf(d1, -C7f, fmaf(d2, -C1f, -d3 * C5f)));
    o[5] = fmaf(d0, C5f, fmaf(d1, -C1f, fmaf(d2,  C7f,  d3 * C3f)));
    o[7] = fmaf(d0, C7f, fmaf(d1, -C5f, fmaf(d2,  C3f, -d3 * C1f)));
}

// o[x] = sum_u a[u] * cos((2x+1)u pi/16)
__device__ __forceinline__ void idct8(const float* a, float* o) {
    float E0 = fmaf(a[2],  C2f, fmaf(a[4],  C4f, fmaf(a[6],  C6f, a[0])));
    float E1 = fmaf(a[2],  C6f, fmaf(a[4], -C4f, fmaf(a[6], -C2f, a[0])));
    float E2 = fmaf(a[2], -C6f, fmaf(a[4], -C4f, fmaf(a[6],  C2f, a[0])));
    float E3 = fmaf(a[2], -C2f, fmaf(a[4],  C4f, fmaf(a[6], -C6f, a[0])));
    float O0 = fmaf(a[1],  C1f, fmaf(a[3],  C3f, fmaf(a[5],  C5f,  a[7] * C7f)));
    float O1 = fmaf(a[1],  C3f, fmaf(a[3], -C7f, fmaf(a[5], -C1f, -a[7] * C5f)));
    float O2 = fmaf(a[1],  C5f, fmaf(a[3], -C1f, fmaf(a[5],  C7f,  a[7] * C3f)));
    float O3 = fmaf(a[1],  C7f, fmaf(a[3], -C5f, fmaf(a[5],  C3f, -a[7] * C1f)));
    o[0] = E0 + O0;  o[7] = E0 - O0;
    o[1] = E1 + O1;  o[6] = E1 - O1;
    o[2] = E2 + O2;  o[5] = E2 - O2;
    o[3] = E3 + O3;  o[4] = E3 - O3;
}

// 8x8 transpose among 8 consecutive lanes (r = lane & 7), 3 butterfly stages.
__device__ __forceinline__ void xpose8(float* a, int r) {
    #pragma unroll
    for (int k = 0; k < 3; k++) {
        const int m = 1 << k;
        const bool hi = (r & m) != 0;
        #pragma unroll
        for (int j0 = 0; j0 < 8; j0++) {
            if ((j0 & m) == 0) {
                const int j1 = j0 | m;
                float send = hi ? a[j0] : a[j1];
                float recv = __shfl_xor_sync(0xffffffffu, send, m);
                if (hi) a[j0] = recv; else a[j1] = recv;
            }
        }
    }
}

// full per-row JPEG chain: row DCT, transpose, col DCT, quant/dequant
// (diff_round), col IDCT, transpose, row IDCT. In-place on a[8].
// rs points at &sRS[ti][2*r]: per-u interleaved (R,S) pairs at stride 16 floats.
__device__ __forceinline__ void jpeg_chain(float* a, int r, const float* rs) {
    float o[8];
    dct8(a, o);          // freq along row
    xpose8(o, r);        // thread now holds partial column v = r
    dct8(o, a);          // a[u] = D[u][v]
    #pragma unroll
    for (int u = 0; u < 8; u++) {
        float2 RS = *(const float2*)&rs[16 * u];
        float tq = a[u] * RS.x;
        float rq = rintf(tq);              // round-half-even == jnp.round
        float dq = tq - rq;
        o[u] = fmaf(dq * dq, dq, rq) * RS.y;
    }
    idct8(o, a);         // spatial x along column v
    xpose8(a, r);        // thread holds row r over v
    idct8(a, o);         // spatial row
    #pragma unroll
    for (int i = 0; i < 8; i++) a[i] = o[i];
}

__global__ __launch_bounds__(256)
void diffjpeg_kernel(const float* __restrict__ img,
                     const float* __restrict__ ytab,
                     const float* __restrict__ ctab,
                     float* __restrict__ out)
{
    // chroma staging planes: 16 rows x 32 cols, stride 36 (16B-aligned, conflict-free)
    __shared__ float sCb[16 * 36];
    __shared__ float sCr[16 * 36];
    // interleaved quant tables: [2i]=0.25*aa/(0.4*tab), [2i+1]=0.25*aa*0.4*tab
    __shared__ float sRS[2][128];

    const int tid = threadIdx.x;

    if (tid < 128) {
        int ti = tid >> 6, i = tid & 63;
        int u = i >> 3, v = i & 7;
        float aa = (u ? 1.0f : C4f) * (v ? 1.0f : C4f);
        float tq = (ti ? ctab[i] : ytab[i]) * 0.4f;
        sRS[ti][2 * i]     = 0.25f * aa / tq;
        sRS[ti][2 * i + 1] = 0.25f * aa * tq;
    }

    // ---------------- front end ------------------------------------------
    // tile = 32 rows x 64 cols; thread: lane = image row (0..31), warp = 8-col seg
    const int tile = blockIdx.x;
    const int bimg = tile >> 7;            // 128 tiles per image
    const int t    = tile & 127;           // 16 x 8 tiles
    const int lane = tid & 31;
    const int wrp  = tid >> 5;             // 0..7
    const int grow = (t >> 3) * 32 + lane;
    const int gcol = (t & 7) * 64 + wrp * 8;
    const int r    = lane & 7;             // row within 8x8 block

    const float* p = img + (size_t)bimg * 3 * HW + grow * W + gcol;
    float4 ra = *(const float4*)(p);
    float4 rb = *(const float4*)(p + 4);
    float4 ga = *(const float4*)(p + HW);
    float4 gb = *(const float4*)(p + HW + 4);
    float4 ba = *(const float4*)(p + 2 * HW);
    float4 bb = *(const float4*)(p + 2 * HW + 4);

    float R[8] = {ra.x, ra.y, ra.z, ra.w, rb.x, rb.y, rb.z, rb.w};
    float G[8] = {ga.x, ga.y, ga.z, ga.w, gb.x, gb.y, gb.z, gb.w};
    float Bc[8] = {ba.x, ba.y, ba.z, ba.w, bb.x, bb.y, bb.z, bb.w};

    float y[8];
    float cbh[4], crh[4];
    #pragma unroll
    for (int j2 = 0; j2 < 4; j2++) {
        float cb0, cb1, cr0, cr1;
        #pragma unroll
        for (int h = 0; h < 2; h++) {
            int j = 2 * j2 + h;
            // coefficients pre-multiplied by 255; Y centered (-128)
            y[j] = fmaf(R[j],  76.245f,   fmaf(G[j],  149.685f,   fmaf(Bc[j], 29.07f, -128.0f)));
            float cb = fmaf(R[j], -43.02768f, fmaf(G[j], -84.47232f,   Bc[j] * 127.5f));
            float cr = fmaf(R[j], 127.5f,     fmaf(G[j], -106.76544f,  Bc[j] * -20.73456f));
            if (h == 0) { cb0 = cb; cr0 = cr; } else { cb1 = cb; cr1 = cr; }
        }
        cbh[j2] = cb0 + cb1;
        crh[j2] = cr0 + cr1;
    }
    // vertical pooling with row partner (lane^1)
    #pragma unroll
    for (int j2 = 0; j2 < 4; j2++) {
        cbh[j2] += __shfl_xor_sync(0xffffffffu, cbh[j2], 1);
        crh[j2] += __shfl_xor_sync(0xffffffffu, crh[j2], 1);
    }
    if (!(lane & 1)) {
        int ci = (lane >> 1) * 36 + wrp * 4;
        *(float4*)&sCb[ci] = make_float4(0.25f * cbh[0], 0.25f * cbh[1],
                                         0.25f * cbh[2], 0.25f * cbh[3]);
        *(float4*)&sCr[ci] = make_float4(0.25f * crh[0], 0.25f * crh[1],
                                         0.25f * crh[2], 0.25f * crh[3]);
    }
    __syncthreads();

    // ---------------- chroma transforms (threads 128..255) ----------------
    if (tid >= 128) {
        int ct  = tid - 128;               // 0..127
        int blk = ct >> 3;                 // 0..15 (0-7 Cb, 8-15 Cr)
        int cr8 = ct & 7;                  // == lane & 7
        float* plane = (blk < 8) ? sCb : sCr;
        int b8 = blk & 7;
        int off = (((b8 >> 2) * 8 + cr8) * 36) + (b8 & 3) * 8;
        float c[8];
        float4 c0 = *(const float4*)&plane[off];
        float4 c1 = *(const float4*)&plane[off + 4];
        c[0] = c0.x; c[1] = c0.y; c[2] = c0.z; c[3] = c0.w;
        c[4] = c1.x; c[5] = c1.y; c[6] = c1.z; c[7] = c1.w;
        jpeg_chain(c, cr8, &sRS[1][2 * cr8]);
        *(float4*)&plane[off]     = make_float4(c[0], c[1], c[2], c[3]);
        *(float4*)&plane[off + 4] = make_float4(c[4], c[5], c[6], c[7]);
    }

    // ---------------- Y transform (all threads, registers only) -----------
    jpeg_chain(y, r, &sRS[0][2 * r]);

    __syncthreads();

    // ---------------- back end --------------------------------------------
    const int ci = (lane >> 1) * 36 + wrp * 4;
    float4 cbq = *(const float4*)&sCb[ci];
    float4 crq = *(const float4*)&sCr[ci];
    float cbp[4] = {cbq.x, cbq.y, cbq.z, cbq.w};
    float crp[4] = {crq.x, crq.y, crq.z, crq.w};

    float4 o0, o1, g0, g1, b0, b1;
    float* pr = &o0.x; float* pr1 = &o1.x;
    float* pg = &g0.x; float* pg1 = &g1.x;
    float* pb = &b0.x; float* pb1 = &b1.x;
    #pragma unroll
    for (int j = 0; j < 8; j++) {
        float yb = y[j] + 128.0f;
        float cc = cbp[j >> 1];
        float cv = crp[j >> 1];
        float ro = fmaf(cv,  1.402f,    yb);
        float go = fmaf(cv, -0.714136f, fmaf(cc, -0.344136f, yb));
        float bo = fmaf(cc,  1.772f,    yb);
        const float inv255 = 1.0f / 255.0f;
        ro = fminf(fmaxf(ro, 0.0f), 255.0f) * inv255;
        go = fminf(fmaxf(go, 0.0f), 255.0f) * inv255;
        bo = fminf(fmaxf(bo, 0.0f), 255.0f) * inv255;
        if (j < 4) { pr[j] = ro; pg[j] = go; pb[j] = bo; }
        else       { pr1[j - 4] = ro; pg1[j - 4] = go; pb1[j - 4] = bo; }
    }
    float* q = out + (size_t)bimg * 3 * HW + grow * W + gcol;
    *(float4*)(q)              = o0;
    *(float4*)(q + 4)          = o1;
    *(float4*)(q + HW)         = g0;
    *(float4*)(q + HW + 4)     = g1;
    *(float4*)(q + 2 * HW)     = b0;
    *(float4*)(q + 2 * HW + 4) = b1;
}

extern "C" void kernel_launch(void* const* d_in, const int* in_sizes, int n_in,
                              void* d_out, int out_size)
{
    const float* img  = (const float*)d_in[0];
    const float* ytab = (const float*)d_in[1];
    const float* ctab = (const float*)d_in[2];
    float* out = (float*)d_out;

    // 32 images * (512/32)*(512/64) tiles = 4096 CTAs
    diffjpeg_kernel<<<4096, 256>>>(img, ytab, ctab, out);
}